// round 7
// baseline (speedup 1.0000x reference)
#include <cuda_runtime.h>
#include <math.h>
#include <stdint.h>

// Problem constants
#define BB 8192
#define KK 8
#define SS 4
#define DD 512
#define SCALE_F 0.044194173824159216f   // 512^-0.5
#define LN_EPS 1e-5f
#define NEG_INF (__int_as_float(0xff800000))

// ---------------------------------------------------------------------------
// Scratch (device globals). NEVER passed as host-side kernel arguments —
// device code resolves them via selectors (host-side symbol references are
// host shadow addresses; on GB300 ATS they silently read host memory).
// Total ~269 MB.
// ---------------------------------------------------------------------------
__device__ float g_bufA[(size_t)BB * SS * DD];   // mhat, then z        (67 MB)
__device__ float g_bufB[(size_t)BB * SS * DD];   // vmix, then wsu      (67 MB)
__device__ float g_bufK[(size_t)BB * KK * DD];   // mix2                (134 MB)
__device__ float g_Aw[SS * DD];                  // (Wk_w^T Qws)  [S,D]
__device__ float g_M[DD * DD];                   // Wq_r^T Wk_r   [D,D]
__device__ float g_Wov[DD * DD];                 // Wo Wv_r       [D,D]

// ---------------------------------------------------------------------------
// Helpers
// ---------------------------------------------------------------------------
__device__ __forceinline__ float warp_sum(float v) {
    #pragma unroll
    for (int o = 16; o; o >>= 1) v += __shfl_xor_sync(0xffffffffu, v, o);
    return v;
}

// dot of two 512-float vectors by one warp; result on all lanes
__device__ __forceinline__ float warp_dot512(const float* __restrict__ a,
                                             const float* __restrict__ b) {
    int lane = threadIdx.x & 31;
    const float4* a4 = reinterpret_cast<const float4*>(a);
    const float4* b4 = reinterpret_cast<const float4*>(b);
    float s = 0.f;
    #pragma unroll
    for (int i = 0; i < 4; i++) {
        float4 x = a4[lane + i * 32];
        float4 y = b4[lane + i * 32];
        s = fmaf(x.x, y.x, s);
        s = fmaf(x.y, y.y, s);
        s = fmaf(x.z, y.z, s);
        s = fmaf(x.w, y.w, s);
    }
    return warp_sum(s);
}

// ---------------------------------------------------------------------------
// Precompute Aw[s,d] = sum_e Qws[s,e] * Wk_w[e,d],
//   where Qws[s,e] = sum_d ws[s,d] * Wq_w[e,d].
// 4 blocks (one per s), 512 threads. Writes g_Aw (device symbol).
// ---------------------------------------------------------------------------
__global__ __launch_bounds__(512) void aw_kernel(
    const float* __restrict__ ws, const float* __restrict__ Wq_w,
    const float* __restrict__ Wk_w) {
    const int s = blockIdx.x;
    const int tid = threadIdx.x;
    const int warp = tid >> 5;
    __shared__ float qs[DD];

    for (int e = warp; e < DD; e += 16) {
        float d = warp_dot512(ws + s * DD, Wq_w + (size_t)e * DD);
        if ((tid & 31) == 0) qs[e] = d;
    }
    __syncthreads();

    float acc = 0.f;
    for (int e = 0; e < DD; e++)
        acc = fmaf(qs[e], Wk_w[(size_t)e * DD + tid], acc);
    g_Aw[s * DD + tid] = acc;
}

// ---------------------------------------------------------------------------
// Small 512x512x512 GEMM: C[m,n] = sum_e opA(m,e) * B[e,n]
//   TRANSA=1: opA(m,e)=A[e,m]  (M = Wq_r^T Wk_r); TRANSA=0: opA=A[m,e] (Wov).
// Output selected in device code: c_sel 0 -> g_M, 1 -> g_Wov.
// ---------------------------------------------------------------------------
template <int TRANSA>
__global__ __launch_bounds__(256) void small_gemm(
    const float* __restrict__ A, const float* __restrict__ B, int c_sel) {
    float* C = (c_sel == 0) ? g_M : g_Wov;
    __shared__ float As[32][33];
    __shared__ float Bs[32][33];
    const int m0 = blockIdx.y * 32;
    const int n0 = blockIdx.x * 32;
    const int tid = threadIdx.x;
    const int tr = tid >> 4;
    const int tc = tid & 15;

    float c00 = 0.f, c01 = 0.f, c10 = 0.f, c11 = 0.f;

    for (int e0 = 0; e0 < DD; e0 += 32) {
        #pragma unroll
        for (int i = tid; i < 1024; i += 256) {
            if (TRANSA) {
                int e = i >> 5, m = i & 31;
                As[e][m] = A[(size_t)(e0 + e) * DD + m0 + m];
            } else {
                int m = i >> 5, e = i & 31;
                As[e][m] = A[(size_t)(m0 + m) * DD + e0 + e];
            }
        }
        #pragma unroll
        for (int i = tid; i < 1024; i += 256) {
            int e = i >> 5, n = i & 31;
            Bs[e][n] = B[(size_t)(e0 + e) * DD + n0 + n];
        }
        __syncthreads();
        #pragma unroll
        for (int e = 0; e < 32; e++) {
            float a0 = As[e][tr * 2], a1 = As[e][tr * 2 + 1];
            float b0 = Bs[e][tc * 2], b1 = Bs[e][tc * 2 + 1];
            c00 = fmaf(a0, b0, c00);
            c01 = fmaf(a0, b1, c01);
            c10 = fmaf(a1, b0, c10);
            c11 = fmaf(a1, b1, c11);
        }
        __syncthreads();
    }
    C[(size_t)(m0 + tr * 2) * DD + n0 + tc * 2] = c00;
    C[(size_t)(m0 + tr * 2) * DD + n0 + tc * 2 + 1] = c01;
    C[(size_t)(m0 + tr * 2 + 1) * DD + n0 + tc * 2] = c10;
    C[(size_t)(m0 + tr * 2 + 1) * DD + n0 + tc * 2 + 1] = c11;
}

// ---------------------------------------------------------------------------
// Main GEMM (NT): C[M,512] = A[M,512] * W^T (W rows K-major).
// All scratch operands resolved in DEVICE code:
//   a_sel: 0=g_bufA 1=g_bufB 2=g_bufK
//   w_sel: -1=Wext  0=g_M    1=g_Wov
//   c_sel: -1=Cext  0=g_bufB 1=g_bufA
// BM=BN=128, BK=16, 256 threads, 8x8 micro-tile. M % 128 == 0.
// ---------------------------------------------------------------------------
#define GBM 128
#define GBN 128
#define GBK 16

__global__ __launch_bounds__(256) void gemm_nt(
    const float* __restrict__ Wext, float* __restrict__ Cext,
    int a_sel, int w_sel, int c_sel, int M) {
    const float* A = (a_sel == 0) ? g_bufA : (a_sel == 1 ? g_bufB : g_bufK);
    const float* W = (w_sel < 0) ? Wext : (w_sel == 0 ? g_M : g_Wov);
    float* C = (c_sel < 0) ? Cext : (c_sel == 0 ? g_bufB : g_bufA);

    __shared__ float As[GBK][GBM];
    __shared__ float Bs[GBK][GBN];

    const int bm = blockIdx.x * GBM;
    const int bn = blockIdx.y * GBN;
    const int tid = threadIdx.x;
    const int tx = tid & 15;
    const int ty = tid >> 4;

    float acc[8][8];
    #pragma unroll
    for (int i = 0; i < 8; i++)
        #pragma unroll
        for (int j = 0; j < 8; j++) acc[i][j] = 0.f;

    for (int k0 = 0; k0 < DD; k0 += GBK) {
        #pragma unroll
        for (int i = 0; i < 2; i++) {
            int idx = tid + i * 256;
            int r = idx >> 2;
            int c4 = (idx & 3) * 4;
            float4 v = *reinterpret_cast<const float4*>(
                A + (size_t)(bm + r) * DD + k0 + c4);
            As[c4 + 0][r] = v.x; As[c4 + 1][r] = v.y;
            As[c4 + 2][r] = v.z; As[c4 + 3][r] = v.w;
        }
        #pragma unroll
        for (int i = 0; i < 2; i++) {
            int idx = tid + i * 256;
            int r = idx >> 2;
            int c4 = (idx & 3) * 4;
            float4 v = *reinterpret_cast<const float4*>(
                W + (size_t)(bn + r) * DD + k0 + c4);
            Bs[c4 + 0][r] = v.x; Bs[c4 + 1][r] = v.y;
            Bs[c4 + 2][r] = v.z; Bs[c4 + 3][r] = v.w;
        }
        __syncthreads();

        #pragma unroll
        for (int k = 0; k < GBK; k++) {
            float a[8], b[8];
            #pragma unroll
            for (int i = 0; i < 8; i++) a[i] = As[k][ty * 8 + i];
            #pragma unroll
            for (int j = 0; j < 8; j++) b[j] = Bs[k][tx * 8 + j];
            #pragma unroll
            for (int i = 0; i < 8; i++)
                #pragma unroll
                for (int j = 0; j < 8; j++)
                    acc[i][j] = fmaf(a[i], b[j], acc[i][j]);
        }
        __syncthreads();
    }

    #pragma unroll
    for (int i = 0; i < 8; i++) {
        float* crow = C + (size_t)(bm + ty * 8 + i) * DD + bn + tx * 8;
        reinterpret_cast<float4*>(crow)[0] =
            make_float4(acc[i][0], acc[i][1], acc[i][2], acc[i][3]);
        reinterpret_cast<float4*>(crow)[1] =
            make_float4(acc[i][4], acc[i][5], acc[i][6], acc[i][7]);
    }
}

// ---------------------------------------------------------------------------
// Write attention: one block (256 thr) per batch b.
//   logits[s,k] = SCALE * Aw[s] . h[b,k]   (masked softmax over k)
//   mhat[b,s]   = sum_k p[s,k] * h[b,k]    -> g_bufA
// ---------------------------------------------------------------------------
__global__ __launch_bounds__(256) void write_attn_kernel(
    const float* __restrict__ hidden,
    const int* __restrict__ mask) {
    const int b = blockIdx.x;
    const int tid = threadIdx.x;
    const int warp = tid >> 5;

    __shared__ float sh[KK][DD];
    __shared__ float logits[SS][KK];
    __shared__ float p[SS][KK];
    __shared__ int smask[KK];

    if (tid < KK) smask[tid] = mask[b * KK + tid];

    for (int i = tid; i < KK * (DD / 4); i += 256) {
        int k = i / (DD / 4), c4 = i % (DD / 4);
        reinterpret_cast<float4*>(sh[k])[c4] =
            reinterpret_cast<const float4*>(hidden + (size_t)(b * KK + k) * DD)[c4];
    }
    __syncthreads();

    for (int pr = warp; pr < SS * KK; pr += 8) {
        int s = pr >> 3, k = pr & 7;
        float d = warp_dot512(g_Aw + s * DD, sh[k]) * SCALE_F;
        if ((tid & 31) == 0) logits[s][k] = d;
    }
    __syncthreads();

    if (tid < SS) {
        int s = tid;
        float m = NEG_INF;
        #pragma unroll
        for (int k = 0; k < KK; k++)
            if (smask[k] != 0) m = fmaxf(m, logits[s][k]);
        float pe[KK], sum = 0.f;
        #pragma unroll
        for (int k = 0; k < KK; k++) {
            float e = (smask[k] != 0) ? expf(logits[s][k] - m) : 0.f;
            pe[k] = e; sum += e;
        }
        float inv = (sum > 0.f) ? 1.f / sum : 0.f;  // all-masked -> zeros
        #pragma unroll
        for (int k = 0; k < KK; k++) p[s][k] = pe[k] * inv;
    }
    __syncthreads();

    #pragma unroll
    for (int s = 0; s < SS; s++) {
        #pragma unroll
        for (int h = 0; h < 2; h++) {
            int d = tid + h * 256;
            float acc = 0.f;
            #pragma unroll
            for (int k = 0; k < KK; k++) acc = fmaf(p[s][k], sh[k][d], acc);
            g_bufA[(size_t)(b * SS + s) * DD + d] = acc;
        }
    }
}

// ---------------------------------------------------------------------------
// wsu = LN(ws[s] + vmix) in-place on g_bufB. One block per (b,s) row.
// ---------------------------------------------------------------------------
__global__ __launch_bounds__(256) void ln_ws_kernel(
    const float* __restrict__ workspace,
    const float* __restrict__ g, const float* __restrict__ bb) {
    const size_t row = blockIdx.x;
    const int s = (int)(row & (SS - 1));
    const int tid = threadIdx.x;
    const int warp = tid >> 5;
    __shared__ float s_part[2][8];
    __shared__ float s_stats[2];

    float vv[2];
    #pragma unroll
    for (int h = 0; h < 2; h++) {
        int d = tid + h * 256;
        vv[h] = workspace[s * DD + d] + g_bufB[row * DD + d];
    }
    float sum = warp_sum(vv[0] + vv[1]);
    float sq = warp_sum(vv[0] * vv[0] + vv[1] * vv[1]);
    if ((tid & 31) == 0) { s_part[0][warp] = sum; s_part[1][warp] = sq; }
    __syncthreads();
    if (tid == 0) {
        float ts = 0.f, tq = 0.f;
        #pragma unroll
        for (int w = 0; w < 8; w++) { ts += s_part[0][w]; tq += s_part[1][w]; }
        float mu = ts * (1.f / DD);
        float var = tq * (1.f / DD) - mu * mu;
        s_stats[0] = mu; s_stats[1] = rsqrtf(var + LN_EPS);
    }
    __syncthreads();
    float mu = s_stats[0], ri = s_stats[1];
    #pragma unroll
    for (int h = 0; h < 2; h++) {
        int d = tid + h * 256;
        g_bufB[row * DD + d] = (vv[h] - mu) * ri * g[d] + bb[d];
    }
}

// ---------------------------------------------------------------------------
// Read attention: one block per batch b.
//   logits[k,s] = SCALE * h[b,k] . z[b,s]; softmax over s
//   mix2[b,k]   = sum_s p[k,s] * wsu[b,s]   -> g_bufK
// z in g_bufA, wsu in g_bufB (device symbols).
// ---------------------------------------------------------------------------
__global__ __launch_bounds__(256) void read_attn_kernel(
    const float* __restrict__ hidden) {
    const int b = blockIdx.x;
    const int tid = threadIdx.x;
    const int warp = tid >> 5;

    __shared__ float sh[KK][DD];
    __shared__ float sz[SS][DD];
    __shared__ float sw[SS][DD];
    __shared__ float logits[KK][SS];
    __shared__ float p[KK][SS];

    for (int i = tid; i < KK * (DD / 4); i += 256) {
        int k = i / (DD / 4), c4 = i % (DD / 4);
        reinterpret_cast<float4*>(sh[k])[c4] =
            reinterpret_cast<const float4*>(hidden + (size_t)(b * KK + k) * DD)[c4];
    }
    for (int i = tid; i < SS * (DD / 4); i += 256) {
        int s = i / (DD / 4), c4 = i % (DD / 4);
        reinterpret_cast<float4*>(sz[s])[c4] =
            reinterpret_cast<const float4*>(g_bufA + (size_t)(b * SS + s) * DD)[c4];
        reinterpret_cast<float4*>(sw[s])[c4] =
            reinterpret_cast<const float4*>(g_bufB + (size_t)(b * SS + s) * DD)[c4];
    }
    __syncthreads();

    for (int pr = warp; pr < KK * SS; pr += 8) {
        int k = pr >> 2, s = pr & 3;
        float d = warp_dot512(sh[k], sz[s]) * SCALE_F;
        if ((tid & 31) == 0) logits[k][s] = d;
    }
    __syncthreads();

    if (tid < KK) {
        int k = tid;
        float m = NEG_INF;
        #pragma unroll
        for (int s = 0; s < SS; s++) m = fmaxf(m, logits[k][s]);
        float pe[SS], sum = 0.f;
        #pragma unroll
        for (int s = 0; s < SS; s++) { pe[s] = expf(logits[k][s] - m); sum += pe[s]; }
        float inv = 1.f / sum;
        #pragma unroll
        for (int s = 0; s < SS; s++) p[k][s] = pe[s] * inv;
    }
    __syncthreads();

    #pragma unroll
    for (int k = 0; k < KK; k++) {
        #pragma unroll
        for (int h = 0; h < 2; h++) {
            int d = tid + h * 256;
            float acc = 0.f;
            #pragma unroll
            for (int s = 0; s < SS; s++) acc = fmaf(p[k][s], sw[s][d], acc);
            g_bufK[(size_t)(b * KK + k) * DD + d] = acc;
        }
    }
}

// ---------------------------------------------------------------------------
// Final LN in-place on out: out = LN(hidden + out). One block per row.
// ---------------------------------------------------------------------------
__global__ __launch_bounds__(256) void out_ln_kernel(
    const float* __restrict__ hidden,
    const float* __restrict__ g, const float* __restrict__ bb,
    float* __restrict__ out) {
    const size_t row = blockIdx.x;
    const int tid = threadIdx.x;
    const int warp = tid >> 5;
    __shared__ float s_part[2][8];
    __shared__ float s_stats[2];

    float vv[2];
    #pragma unroll
    for (int h = 0; h < 2; h++) {
        int d = tid + h * 256;
        vv[h] = hidden[row * DD + d] + out[row * DD + d];
    }
    float sum = warp_sum(vv[0] + vv[1]);
    float sq = warp_sum(vv[0] * vv[0] + vv[1] * vv[1]);
    if ((tid & 31) == 0) { s_part[0][warp] = sum; s_part[1][warp] = sq; }
    __syncthreads();
    if (tid == 0) {
        float ts = 0.f, tq = 0.f;
        #pragma unroll
        for (int w = 0; w < 8; w++) { ts += s_part[0][w]; tq += s_part[1][w]; }
        float mu = ts * (1.f / DD);
        float var = tq * (1.f / DD) - mu * mu;
        s_stats[0] = mu; s_stats[1] = rsqrtf(var + LN_EPS);
    }
    __syncthreads();
    float mu = s_stats[0], ri = s_stats[1];
    #pragma unroll
    for (int h = 0; h < 2; h++) {
        int d = tid + h * 256;
        out[row * DD + d] = (vv[h] - mu) * ri * g[d] + bb[d];
    }
}

// ---------------------------------------------------------------------------
// Launch — kernel launches ONLY; only harness pointers cross the boundary.
// ---------------------------------------------------------------------------
extern "C" void kernel_launch(void* const* d_in, const int* in_sizes, int n_in,
                              void* d_out, int out_size) {
    const float* hidden = (const float*)d_in[0];
    const int* mask = (const int*)d_in[1];
    const float* workspace = (const float*)d_in[2];
    const float* Wq_w = (const float*)d_in[3];
    const float* Wk_w = (const float*)d_in[4];
    const float* Wv_w = (const float*)d_in[5];
    const float* Wq_r = (const float*)d_in[6];
    const float* Wk_r = (const float*)d_in[7];
    const float* Wv_r = (const float*)d_in[8];
    const float* Wo = (const float*)d_in[9];
    const float* g_ws_p = (const float*)d_in[10];
    const float* b_ws_p = (const float*)d_in[11];
    const float* g_out_p = (const float*)d_in[12];
    const float* b_out_p = (const float*)d_in[13];
    float* out = (float*)d_out;

    dim3 sg(DD / 32, DD / 32);

    // Batch-independent precomputes
    aw_kernel<<<SS, 512>>>(workspace, Wq_w, Wk_w);        // g_Aw
    small_gemm<1><<<sg, 256>>>(Wq_r, Wk_r, 0);            // g_M   = Wq_r^T Wk_r
    small_gemm<0><<<sg, 256>>>(Wo, Wv_r, 1);              // g_Wov = Wo Wv_r

    // Write attention -> mhat (g_bufA)
    write_attn_kernel<<<BB, 256>>>(hidden, mask);

    // vmix = mhat @ Wv_w^T -> g_bufB   [32768, 512]
    {
        dim3 grid((BB * SS) / GBM, DD / GBN);
        gemm_nt<<<grid, 256>>>(Wv_w, nullptr, /*a*/0, /*w*/-1, /*c*/0, BB * SS);
    }

    // wsu = LN(ws + vmix), in-place g_bufB
    ln_ws_kernel<<<BB * SS, 256>>>(workspace, g_ws_p, b_ws_p);

    // z = wsu @ M^T -> g_bufA   [32768, 512]
    {
        dim3 grid((BB * SS) / GBM, DD / GBN);
        gemm_nt<<<grid, 256>>>(nullptr, nullptr, /*a*/1, /*w*/0, /*c*/1, BB * SS);
    }

    // Read attention -> mix2 (g_bufK)
    read_attn_kernel<<<BB, 256>>>(hidden);

    // proj = mix2 @ Wov^T -> out   [65536, 512]
    {
        dim3 grid((BB * KK) / GBM, DD / GBN);
        gemm_nt<<<grid, 256>>>(nullptr, out, /*a*/2, /*w*/1, /*c*/-1, BB * KK);
    }

    // out = LN(hidden + proj), in-place
    out_ln_kernel<<<BB * KK, 256>>>(hidden, g_out_p, b_out_p, out);
}

// round 8
// speedup vs baseline: 2.6047x; 2.6047x over previous
#include <cuda_runtime.h>
#include <math.h>
#include <stdint.h>

// Problem constants
#define BB 8192
#define KK 8
#define SS 4
#define DD 512
#define SCALE_F 0.044194173824159216f   // 512^-0.5
#define LN_EPS 1e-5f
#define NEG_INF (__int_as_float(0xff800000))

// ---------------------------------------------------------------------------
// Scratch (device globals). NEVER passed as host-side kernel arguments —
// device code resolves them via selectors (host-side symbol references are
// host shadow addresses; GB300 ATS silently reads host memory).
// ---------------------------------------------------------------------------
__device__ float g_bufA[(size_t)BB * SS * DD];   // mhat, then z
__device__ float g_bufB[(size_t)BB * SS * DD];   // vmix, then wsu
__device__ float g_bufK[(size_t)BB * KK * DD];   // wsup (projected wsu)
__device__ float g_Aw[SS * DD];                  // Wk_w^T Qws   [S,D]
__device__ float g_M[DD * DD];                   // Wq_r^T Wk_r  [D,D]
__device__ float g_Wov[DD * DD];                 // Wo Wv_r      [D,D]

// ---------------------------------------------------------------------------
// Helpers
// ---------------------------------------------------------------------------
__device__ __forceinline__ float warp_sum(float v) {
    #pragma unroll
    for (int o = 16; o; o >>= 1) v += __shfl_xor_sync(0xffffffffu, v, o);
    return v;
}

__device__ __forceinline__ float warp_dot512(const float* __restrict__ a,
                                             const float* __restrict__ b) {
    int lane = threadIdx.x & 31;
    const float4* a4 = reinterpret_cast<const float4*>(a);
    const float4* b4 = reinterpret_cast<const float4*>(b);
    float s = 0.f;
    #pragma unroll
    for (int i = 0; i < 4; i++) {
        float4 x = a4[lane + i * 32];
        float4 y = b4[lane + i * 32];
        s = fmaf(x.x, y.x, s);
        s = fmaf(x.y, y.y, s);
        s = fmaf(x.z, y.z, s);
        s = fmaf(x.w, y.w, s);
    }
    return warp_sum(s);
}

__device__ __forceinline__ uint32_t f2tf32(float f) {
    uint32_t r;
    asm("cvt.rna.tf32.f32 %0, %1;" : "=r"(r) : "f"(f));
    return r;
}

__device__ __forceinline__ void mma_tf32(float* c, const uint32_t* a,
                                         const uint32_t* b) {
    asm volatile(
        "mma.sync.aligned.m16n8k8.row.col.f32.tf32.tf32.f32 "
        "{%0,%1,%2,%3}, {%4,%5,%6,%7}, {%8,%9}, {%0,%1,%2,%3};\n"
        : "+f"(c[0]), "+f"(c[1]), "+f"(c[2]), "+f"(c[3])
        : "r"(a[0]), "r"(a[1]), "r"(a[2]), "r"(a[3]), "r"(b[0]), "r"(b[1]));
}

// ---------------------------------------------------------------------------
// Precompute Aw[s,d] = sum_e Qws[s,e]*Wk_w[e,d], Qws = ws @ Wq_w^T
// ---------------------------------------------------------------------------
__global__ __launch_bounds__(512) void aw_kernel(
    const float* __restrict__ ws, const float* __restrict__ Wq_w,
    const float* __restrict__ Wk_w) {
    const int s = blockIdx.x;
    const int tid = threadIdx.x;
    const int warp = tid >> 5;
    __shared__ float qs[DD];

    for (int e = warp; e < DD; e += 16) {
        float d = warp_dot512(ws + s * DD, Wq_w + (size_t)e * DD);
        if ((tid & 31) == 0) qs[e] = d;
    }
    __syncthreads();

    float acc = 0.f;
    for (int e = 0; e < DD; e++)
        acc = fmaf(qs[e], Wk_w[(size_t)e * DD + tid], acc);
    g_Aw[s * DD + tid] = acc;
}

// ---------------------------------------------------------------------------
// Small 512^3 GEMM (fp32, exact): C = opA(A)*B. c_sel: 0->g_M, 1->g_Wov.
// ---------------------------------------------------------------------------
template <int TRANSA>
__global__ __launch_bounds__(256) void small_gemm(
    const float* __restrict__ A, const float* __restrict__ B, int c_sel) {
    float* C = (c_sel == 0) ? g_M : g_Wov;
    __shared__ float As[32][33];
    __shared__ float Bs[32][33];
    const int m0 = blockIdx.y * 32;
    const int n0 = blockIdx.x * 32;
    const int tid = threadIdx.x;
    const int tr = tid >> 4;
    const int tc = tid & 15;

    float c00 = 0.f, c01 = 0.f, c10 = 0.f, c11 = 0.f;

    for (int e0 = 0; e0 < DD; e0 += 32) {
        #pragma unroll
        for (int i = tid; i < 1024; i += 256) {
            if (TRANSA) {
                int e = i >> 5, m = i & 31;
                As[e][m] = A[(size_t)(e0 + e) * DD + m0 + m];
            } else {
                int m = i >> 5, e = i & 31;
                As[e][m] = A[(size_t)(m0 + m) * DD + e0 + e];
            }
        }
        #pragma unroll
        for (int i = tid; i < 1024; i += 256) {
            int e = i >> 5, n = i & 31;
            Bs[e][n] = B[(size_t)(e0 + e) * DD + n0 + n];
        }
        __syncthreads();
        #pragma unroll
        for (int e = 0; e < 32; e++) {
            float a0 = As[e][tr * 2], a1 = As[e][tr * 2 + 1];
            float b0 = Bs[e][tc * 2], b1 = Bs[e][tc * 2 + 1];
            c00 = fmaf(a0, b0, c00);
            c01 = fmaf(a0, b1, c01);
            c10 = fmaf(a1, b0, c10);
            c11 = fmaf(a1, b1, c11);
        }
        __syncthreads();
    }
    C[(size_t)(m0 + tr * 2) * DD + n0 + tc * 2] = c00;
    C[(size_t)(m0 + tr * 2) * DD + n0 + tc * 2 + 1] = c01;
    C[(size_t)(m0 + tr * 2 + 1) * DD + n0 + tc * 2] = c10;
    C[(size_t)(m0 + tr * 2 + 1) * DD + n0 + tc * 2 + 1] = c11;
}

// ---------------------------------------------------------------------------
// tf32 tensor-core GEMM (NT): C[M,*] = A[M,512] @ W[n,:]^T
// Tiles: 128x128x32; 8 warps (2x4), warp-tile 64x32 via m16n8k8.
// Operand/output selection in device code:
//   a_sel: 0=g_bufA 1=g_bufB
//   wmode: 0=Wext(N=512)  1=cols[0,512)->g_M, [512,1024)->g_Wov
//   cmode: 0=g_bufB        1=cols[0,512)->g_bufA, [512,1024)->g_bufK
// ---------------------------------------------------------------------------
#define TM 128
#define TN 128
#define TK 32

__global__ __launch_bounds__(256) void gemm_tf32(
    const float* __restrict__ Wext,
    int a_sel, int wmode, int cmode, int M) {
    const float* A = (a_sel == 0) ? g_bufA : g_bufB;
    const int bm = blockIdx.x * TM;
    const int bn = blockIdx.y * TN;

    const float* W;
    int wn0;
    if (wmode == 0) { W = Wext; wn0 = bn; }
    else { W = (bn < 512) ? g_M : g_Wov; wn0 = bn & 511; }

    float* C;
    int cn0;
    if (cmode == 0) { C = g_bufB; cn0 = bn; }
    else { C = (bn < 512) ? g_bufA : g_bufK; cn0 = bn & 511; }

    __shared__ uint32_t As[TM][36];   // padded: conflict-free fragment loads
    __shared__ uint32_t Bs[TN][36];

    const int tid = threadIdx.x;
    const int lane = tid & 31;
    const int warp = tid >> 5;
    const int wm = warp & 1;          // 2 warps along M (64 rows each)
    const int wn = warp >> 1;         // 4 warps along N (32 cols each)
    const int gid = lane >> 2;
    const int tig = lane & 3;

    float acc[4][4][4];
    #pragma unroll
    for (int i = 0; i < 4; i++)
        #pragma unroll
        for (int j = 0; j < 4; j++)
            #pragma unroll
            for (int r = 0; r < 4; r++) acc[i][j][r] = 0.f;

    // staging registers: 4 float4 per operand per tile
    float4 ra[4], rw[4];

    // preload k-tile 0
    #pragma unroll
    for (int i = 0; i < 4; i++) {
        int idx = tid + i * 256;
        int r = idx >> 3, c = (idx & 7) * 4;
        ra[i] = *reinterpret_cast<const float4*>(A + (size_t)(bm + r) * DD + c);
        rw[i] = *reinterpret_cast<const float4*>(W + (size_t)(wn0 + r) * DD + c);
    }

    for (int t = 0; t < DD / TK; t++) {
        // commit staged tile to smem (convert to tf32 bit patterns)
        #pragma unroll
        for (int i = 0; i < 4; i++) {
            int idx = tid + i * 256;
            int r = idx >> 3, c = (idx & 7) * 4;
            As[r][c + 0] = f2tf32(ra[i].x); As[r][c + 1] = f2tf32(ra[i].y);
            As[r][c + 2] = f2tf32(ra[i].z); As[r][c + 3] = f2tf32(ra[i].w);
            Bs[r][c + 0] = f2tf32(rw[i].x); Bs[r][c + 1] = f2tf32(rw[i].y);
            Bs[r][c + 2] = f2tf32(rw[i].z); Bs[r][c + 3] = f2tf32(rw[i].w);
        }
        __syncthreads();

        // prefetch next k-tile while computing
        if (t + 1 < DD / TK) {
            int k0 = (t + 1) * TK;
            #pragma unroll
            for (int i = 0; i < 4; i++) {
                int idx = tid + i * 256;
                int r = idx >> 3, c = (idx & 7) * 4;
                ra[i] = *reinterpret_cast<const float4*>(
                    A + (size_t)(bm + r) * DD + k0 + c);
                rw[i] = *reinterpret_cast<const float4*>(
                    W + (size_t)(wn0 + r) * DD + k0 + c);
            }
        }

        #pragma unroll
        for (int ks = 0; ks < 4; ks++) {
            uint32_t af[4][4], bf[4][2];
            #pragma unroll
            for (int mt = 0; mt < 4; mt++) {
                int r0 = wm * 64 + mt * 16 + gid;
                af[mt][0] = As[r0][ks * 8 + tig];
                af[mt][1] = As[r0 + 8][ks * 8 + tig];
                af[mt][2] = As[r0][ks * 8 + tig + 4];
                af[mt][3] = As[r0 + 8][ks * 8 + tig + 4];
            }
            #pragma unroll
            for (int nt = 0; nt < 4; nt++) {
                int c0 = wn * 32 + nt * 8 + gid;
                bf[nt][0] = Bs[c0][ks * 8 + tig];
                bf[nt][1] = Bs[c0][ks * 8 + tig + 4];
            }
            #pragma unroll
            for (int mt = 0; mt < 4; mt++)
                #pragma unroll
                for (int nt = 0; nt < 4; nt++)
                    mma_tf32(acc[mt][nt], af[mt], bf[nt]);
        }
        __syncthreads();
    }

    // epilogue
    #pragma unroll
    for (int mt = 0; mt < 4; mt++) {
        #pragma unroll
        for (int nt = 0; nt < 4; nt++) {
            int grow = bm + wm * 64 + mt * 16 + gid;
            int gcol = cn0 + wn * 32 + nt * 8 + 2 * tig;
            *reinterpret_cast<float2*>(&C[(size_t)grow * DD + gcol]) =
                make_float2(acc[mt][nt][0], acc[mt][nt][1]);
            *reinterpret_cast<float2*>(&C[(size_t)(grow + 8) * DD + gcol]) =
                make_float2(acc[mt][nt][2], acc[mt][nt][3]);
        }
    }
}

// ---------------------------------------------------------------------------
// Write attention -> mhat (g_bufA). One block per batch b.
// ---------------------------------------------------------------------------
__global__ __launch_bounds__(256) void write_attn_kernel(
    const float* __restrict__ hidden,
    const int* __restrict__ mask) {
    const int b = blockIdx.x;
    const int tid = threadIdx.x;
    const int warp = tid >> 5;

    __shared__ float sh[KK][DD];
    __shared__ float logits[SS][KK];
    __shared__ float p[SS][KK];
    __shared__ int smask[KK];

    if (tid < KK) smask[tid] = mask[b * KK + tid];

    for (int i = tid; i < KK * (DD / 4); i += 256) {
        int k = i / (DD / 4), c4 = i % (DD / 4);
        reinterpret_cast<float4*>(sh[k])[c4] =
            reinterpret_cast<const float4*>(hidden + (size_t)(b * KK + k) * DD)[c4];
    }
    __syncthreads();

    for (int pr = warp; pr < SS * KK; pr += 8) {
        int s = pr >> 3, k = pr & 7;
        float d = warp_dot512(g_Aw + s * DD, sh[k]) * SCALE_F;
        if ((tid & 31) == 0) logits[s][k] = d;
    }
    __syncthreads();

    if (tid < SS) {
        int s = tid;
        float m = NEG_INF;
        #pragma unroll
        for (int k = 0; k < KK; k++)
            if (smask[k] != 0) m = fmaxf(m, logits[s][k]);
        float pe[KK], sum = 0.f;
        #pragma unroll
        for (int k = 0; k < KK; k++) {
            float e = (smask[k] != 0) ? expf(logits[s][k] - m) : 0.f;
            pe[k] = e; sum += e;
        }
        float inv = (sum > 0.f) ? 1.f / sum : 0.f;
        #pragma unroll
        for (int k = 0; k < KK; k++) p[s][k] = pe[k] * inv;
    }
    __syncthreads();

    #pragma unroll
    for (int s = 0; s < SS; s++) {
        #pragma unroll
        for (int h = 0; h < 2; h++) {
            int d = tid + h * 256;
            float acc = 0.f;
            #pragma unroll
            for (int k = 0; k < KK; k++) acc = fmaf(p[s][k], sh[k][d], acc);
            g_bufA[(size_t)(b * SS + s) * DD + d] = acc;
        }
    }
}

// ---------------------------------------------------------------------------
// wsu = LN(ws[s] + vmix) in-place on g_bufB. One block per (b,s) row.
// ---------------------------------------------------------------------------
__global__ __launch_bounds__(256) void ln_ws_kernel(
    const float* __restrict__ workspace,
    const float* __restrict__ g, const float* __restrict__ bb) {
    const size_t row = blockIdx.x;
    const int s = (int)(row & (SS - 1));
    const int tid = threadIdx.x;
    const int warp = tid >> 5;
    __shared__ float s_part[2][8];
    __shared__ float s_stats[2];

    float vv[2];
    #pragma unroll
    for (int h = 0; h < 2; h++) {
        int d = tid + h * 256;
        vv[h] = workspace[s * DD + d] + g_bufB[row * DD + d];
    }
    float sum = warp_sum(vv[0] + vv[1]);
    float sq = warp_sum(vv[0] * vv[0] + vv[1] * vv[1]);
    if ((tid & 31) == 0) { s_part[0][warp] = sum; s_part[1][warp] = sq; }
    __syncthreads();
    if (tid == 0) {
        float ts = 0.f, tq = 0.f;
        #pragma unroll
        for (int w = 0; w < 8; w++) { ts += s_part[0][w]; tq += s_part[1][w]; }
        float mu = ts * (1.f / DD);
        float var = tq * (1.f / DD) - mu * mu;
        s_stats[0] = mu; s_stats[1] = rsqrtf(var + LN_EPS);
    }
    __syncthreads();
    float mu = s_stats[0], ri = s_stats[1];
    #pragma unroll
    for (int h = 0; h < 2; h++) {
        int d = tid + h * 256;
        g_bufB[row * DD + d] = (vv[h] - mu) * ri * g[d] + bb[d];
    }
}

// ---------------------------------------------------------------------------
// Read attention: one block per batch b.
//   logits[k,s] = SCALE * h[b,k] . z[b,s]  (z in g_bufA); softmax over s
//   out[b,k,:]  = sum_s p[k,s] * wsup[b,s,:]  (wsup in g_bufK)
// ---------------------------------------------------------------------------
__global__ __launch_bounds__(256) void read_attn_kernel(
    const float* __restrict__ hidden, float* __restrict__ out) {
    const int b = blockIdx.x;
    const int tid = threadIdx.x;
    const int warp = tid >> 5;

    __shared__ float sh[KK][DD];
    __shared__ float sz[SS][DD];
    __shared__ float sw[SS][DD];
    __shared__ float logits[KK][SS];
    __shared__ float p[KK][SS];

    for (int i = tid; i < KK * (DD / 4); i += 256) {
        int k = i / (DD / 4), c4 = i % (DD / 4);
        reinterpret_cast<float4*>(sh[k])[c4] =
            reinterpret_cast<const float4*>(hidden + (size_t)(b * KK + k) * DD)[c4];
    }
    for (int i = tid; i < SS * (DD / 4); i += 256) {
        int s = i / (DD / 4), c4 = i % (DD / 4);
        reinterpret_cast<float4*>(sz[s])[c4] =
            reinterpret_cast<const float4*>(g_bufA + (size_t)(b * SS + s) * DD)[c4];
        reinterpret_cast<float4*>(sw[s])[c4] =
            reinterpret_cast<const float4*>(g_bufK + (size_t)(b * SS + s) * DD)[c4];
    }
    __syncthreads();

    for (int pr = warp; pr < KK * SS; pr += 8) {
        int k = pr >> 2, s = pr & 3;
        float d = warp_dot512(sh[k], sz[s]) * SCALE_F;
        if ((tid & 31) == 0) logits[k][s] = d;
    }
    __syncthreads();

    if (tid < KK) {
        int k = tid;
        float m = NEG_INF;
        #pragma unroll
        for (int s = 0; s < SS; s++) m = fmaxf(m, logits[k][s]);
        float pe[SS], sum = 0.f;
        #pragma unroll
        for (int s = 0; s < SS; s++) { pe[s] = expf(logits[k][s] - m); sum += pe[s]; }
        float inv = 1.f / sum;
        #pragma unroll
        for (int s = 0; s < SS; s++) p[k][s] = pe[s] * inv;
    }
    __syncthreads();

    #pragma unroll
    for (int k = 0; k < KK; k++) {
        #pragma unroll
        for (int h = 0; h < 2; h++) {
            int d = tid + h * 256;
            float acc = 0.f;
            #pragma unroll
            for (int s = 0; s < SS; s++) acc = fmaf(p[k][s], sw[s][d], acc);
            out[(size_t)(b * KK + k) * DD + d] = acc;
        }
    }
}

// ---------------------------------------------------------------------------
// Final LN in-place on out: out = LN(hidden + out). One block per row.
// ---------------------------------------------------------------------------
__global__ __launch_bounds__(256) void out_ln_kernel(
    const float* __restrict__ hidden,
    const float* __restrict__ g, const float* __restrict__ bb,
    float* __restrict__ out) {
    const size_t row = blockIdx.x;
    const int tid = threadIdx.x;
    const int warp = tid >> 5;
    __shared__ float s_part[2][8];
    __shared__ float s_stats[2];

    float vv[2];
    #pragma unroll
    for (int h = 0; h < 2; h++) {
        int d = tid + h * 256;
        vv[h] = hidden[row * DD + d] + out[row * DD + d];
    }
    float sum = warp_sum(vv[0] + vv[1]);
    float sq = warp_sum(vv[0] * vv[0] + vv[1] * vv[1]);
    if ((tid & 31) == 0) { s_part[0][warp] = sum; s_part[1][warp] = sq; }
    __syncthreads();
    if (tid == 0) {
        float ts = 0.f, tq = 0.f;
        #pragma unroll
        for (int w = 0; w < 8; w++) { ts += s_part[0][w]; tq += s_part[1][w]; }
        float mu = ts * (1.f / DD);
        float var = tq * (1.f / DD) - mu * mu;
        s_stats[0] = mu; s_stats[1] = rsqrtf(var + LN_EPS);
    }
    __syncthreads();
    float mu = s_stats[0], ri = s_stats[1];
    #pragma unroll
    for (int h = 0; h < 2; h++) {
        int d = tid + h * 256;
        out[row * DD + d] = (vv[h] - mu) * ri * g[d] + bb[d];
    }
}

// ---------------------------------------------------------------------------
// Launch — kernel launches ONLY; only harness pointers cross the boundary.
// ---------------------------------------------------------------------------
extern "C" void kernel_launch(void* const* d_in, const int* in_sizes, int n_in,
                              void* d_out, int out_size) {
    const float* hidden = (const float*)d_in[0];
    const int* mask = (const int*)d_in[1];
    const float* workspace = (const float*)d_in[2];
    const float* Wq_w = (const float*)d_in[3];
    const float* Wk_w = (const float*)d_in[4];
    const float* Wv_w = (const float*)d_in[5];
    const float* Wq_r = (const float*)d_in[6];
    const float* Wk_r = (const float*)d_in[7];
    const float* Wv_r = (const float*)d_in[8];
    const float* Wo = (const float*)d_in[9];
    const float* g_ws_p = (const float*)d_in[10];
    const float* b_ws_p = (const float*)d_in[11];
    const float* g_out_p = (const float*)d_in[12];
    const float* b_out_p = (const float*)d_in[13];
    float* out = (float*)d_out;

    dim3 sg(DD / 32, DD / 32);

    // Batch-independent precomputes (fp32 exact)
    aw_kernel<<<SS, 512>>>(workspace, Wq_w, Wk_w);        // g_Aw
    small_gemm<1><<<sg, 256>>>(Wq_r, Wk_r, 0);            // g_M   = Wq_r^T Wk_r
    small_gemm<0><<<sg, 256>>>(Wo, Wv_r, 1);              // g_Wov = Wo Wv_r

    // Write attention -> mhat (g_bufA)
    write_attn_kernel<<<BB, 256>>>(hidden, mask);

    // vmix = mhat @ Wv_w^T -> g_bufB   [32768, 512]  (tf32 TC)
    {
        dim3 grid((BB * SS) / TM, DD / TN);
        gemm_tf32<<<grid, 256>>>(Wv_w, /*a*/0, /*w*/0, /*c*/0, BB * SS);
    }

    // wsu = LN(ws + vmix), in-place g_bufB
    ln_ws_kernel<<<BB * SS, 256>>>(workspace, g_ws_p, b_ws_p);

    // [z | wsup] = wsu @ [M | Wov]^T -> g_bufA | g_bufK   [32768, 1024] (tf32 TC)
    {
        dim3 grid((BB * SS) / TM, (2 * DD) / TN);
        gemm_tf32<<<grid, 256>>>(nullptr, /*a*/1, /*w*/1, /*c*/1, BB * SS);
    }

    // Read attention: softmax(h.z) mix of wsup -> out
    read_attn_kernel<<<BB, 256>>>(hidden, out);

    // out = LN(hidden + out), in-place
    out_ln_kernel<<<BB * KK, 256>>>(hidden, g_out_p, b_out_p, out);
}